// round 12
// baseline (speedup 1.0000x reference)
#include <cuda_runtime.h>
#include <cuda_bf16.h>
#include <cstdint>

// Problem constants
#define T_STEPS 256
#define BATCH   128
#define HID     1024
#define LAT     128
#define PIECE   128

#define NBLK 128             // one CTA per 8 hidden units (32 gate cols); 1 CTA/SM
#define NTHR 512             // 16 warps = 4/SMSP; k-split: wid>>3 = k-half
#define KCH  16              // k per streamed chunk (per warp)
#define NCHUNK 32            // chunks per warp (covers its 512-k half)

// B: 33 rows (32 gates + 1 FC) x 1024 k, row stride 1032 elems (2064 B)
#define BSTR 1032
#define OFF_BHI 0
#define OFF_BLO (33 * BSTR * 2)            // 68112
#define OFF_A   (2 * 33 * BSTR * 2)        // 136224 ; per-warp 3-stage staging
#define ASTR 24                            // A row: 16 k + 8 pad -> 48 B stride
#define A_COMP  (16 * ASTR * 2)            // 768 B (one component, 16 rows)
#define A_WSTG  (2 * A_COMP)               // 1536 B (hi+lo)
#define A_WREG  (3 * A_WSTG)               // 4608 B per warp
#define OFF_MISC (OFF_A + 16 * A_WREG)     // 209952 ; bsum[32]
#define SMEM_BYTES (OFF_MISC + 256)        // 210208

typedef unsigned long long ull;

// Persistent state
__device__ __nv_bfloat16 g_hsp[2][2][BATCH * HID];  // [time buf][hi/lo][b][k]
__device__ unsigned g_bar;                          // monotonic grid barrier

// ---------------- helpers ----------------
__device__ __forceinline__ uint32_t smem_u32(const void* p) {
    uint32_t a;
    asm("{ .reg .u64 t; cvta.to.shared.u64 t, %1; cvt.u32.u64 %0, t; }"
        : "=r"(a) : "l"(p));
    return a;
}
__device__ __forceinline__ void cp_async16(uint32_t sdst, const void* gsrc) {
    asm volatile("cp.async.cg.shared.global [%0], [%1], 16;\n" :: "r"(sdst), "l"(gsrc));
}
__device__ __forceinline__ void cp_commit() { asm volatile("cp.async.commit_group;\n"); }
__device__ __forceinline__ void cp_wait0()  { asm volatile("cp.async.wait_group 0;\n"); }
__device__ __forceinline__ void cp_wait1()  { asm volatile("cp.async.wait_group 1;\n"); }
__device__ __forceinline__ void cp_wait2()  { asm volatile("cp.async.wait_group 2;\n"); }

__device__ __forceinline__ void ldsm4(uint32_t* r, uint32_t addr) {
    asm volatile("ldmatrix.sync.aligned.m8n8.x4.shared.b16 {%0,%1,%2,%3}, [%4];"
                 : "=r"(r[0]), "=r"(r[1]), "=r"(r[2]), "=r"(r[3]) : "r"(addr));
}
__device__ __forceinline__ void ldsm2(uint32_t* r, uint32_t addr) {
    asm volatile("ldmatrix.sync.aligned.m8n8.x2.shared.b16 {%0,%1}, [%2];"
                 : "=r"(r[0]), "=r"(r[1]) : "r"(addr));
}
// mma.sync m16n8k16 row.col f32.bf16.bf16.f32
__device__ __forceinline__ void mma16816(float* d, const uint32_t* a, const uint32_t* b) {
    asm volatile(
        "mma.sync.aligned.m16n8k16.row.col.f32.bf16.bf16.f32 "
        "{%0,%1,%2,%3}, {%4,%5,%6,%7}, {%8,%9}, {%0,%1,%2,%3};"
        : "+f"(d[0]), "+f"(d[1]), "+f"(d[2]), "+f"(d[3])
        : "r"(a[0]), "r"(a[1]), "r"(a[2]), "r"(a[3]), "r"(b[0]), "r"(b[1]));
}
__device__ __forceinline__ float sigf(float x) { return 1.0f / (1.0f + __expf(-x)); }

// Grid barrier (128 co-resident CTAs; monotonic counter, graph-replay safe)
__device__ __forceinline__ void grid_bar() {
    __threadfence();
    __syncthreads();
    if (threadIdx.x == 0) {
        unsigned my = atomicAdd(&g_bar, 1u);
        unsigned target = my - (my % NBLK) + NBLK;
        while (*(volatile unsigned*)&g_bar < target) { __nanosleep(40); }
        __threadfence();
    }
    __syncthreads();
}

// ---------------- persistent mma.sync kernel ----------------
// Per step, per CTA: D[128 x 33] = h_split[128 x 1024] . B^T
//   B row n = u*4+g -> w_hh[g*HID+blk*8+u][:] ; row 32 -> W_fc[blk][:]
// Split bf16: D = Ahi.Bhi + Ahi.Blo + Alo.Bhi (fp32 accum)
// k-split across warp groups: warps 0-7 k<512 (rows wr*16..+15),
// warps 8-15 k>=512 (same rows); partial D exchanged via smem per step.
extern "C" __global__ void __launch_bounds__(NTHR, 1)
lstm_mma_kernel(const float* __restrict__ z,
                const float* __restrict__ w_ih,
                const float* __restrict__ w_hh,
                const float* __restrict__ b_ih,
                const float* __restrict__ b_hh,
                const float* __restrict__ W_fc,
                const float* __restrict__ b_fc,
                float* __restrict__ out)
{
    extern __shared__ char smem[];
    const uint32_t sbase = smem_u32(smem);
    float* bsum = (float*)(smem + OFF_MISC);     // [32] gate biases
    float* Xg   = (float*)(smem + OFF_A);        // [32][128] f32, t=0 only (alias)
    float* exch = (float*)(smem + OFF_A);        // [256][21] partial-D (alias, t>=1)

    const int tid  = threadIdx.x;
    const int blk  = blockIdx.x;
    const int wid  = tid >> 5;
    const int lane = tid & 31;
    const int kl   = wid >> 3;       // k-half
    const int wr   = wid & 7;        // row-warp: rows wr*16..+15

    // ---------- prologue: build B (split bf16), 33 rows ----------
    {
        uint4 zz = make_uint4(0, 0, 0, 0);
        uint4* bb = (uint4*)smem;
        for (int i = tid; i < (2 * 33 * BSTR * 2) / 16; i += NTHR) bb[i] = zz;
    }
    __syncthreads();
    for (int e = tid; e < 33 * HID; e += NTHR) {
        int n = e >> 10, k = e & 1023;
        float x;
        if (n < 32) {
            int u = n >> 2, g = n & 3;
            x = w_hh[(size_t)(g * HID + blk * 8 + u) * HID + k];
        } else {
            x = W_fc[(size_t)blk * HID + k];
        }
        __nv_bfloat16 hi = __float2bfloat16(x);
        __nv_bfloat16 lo = __float2bfloat16(x - __bfloat162float(hi));
        *(__nv_bfloat16*)(smem + OFF_BHI + ((size_t)n * BSTR + k) * 2) = hi;
        *(__nv_bfloat16*)(smem + OFF_BLO + ((size_t)n * BSTR + k) * 2) = lo;
    }
    if (tid < 32) {
        int u = tid >> 2, g = tid & 3;
        bsum[tid] = b_ih[g * HID + blk * 8 + u] + b_hh[g * HID + blk * 8 + u];
    }
    const float bfc = b_fc[blk];

    // Step-0 input gates: Xg[n][b] = z[b,:] . w_ih[row(n),:]
    for (int d = tid; d < 32 * BATCH; d += NTHR) {
        int n = d >> 7, b = d & 127;
        int u = n >> 2, g = n & 3;
        const float* wi = w_ih + (size_t)(g * HID + blk * 8 + u) * LAT;
        const float* zb = z + (size_t)b * LAT;
        float s = 0.f;
        #pragma unroll 4
        for (int l = 0; l < LAT; ++l) s += zb[l] * wi[l];
        Xg[n * BATCH + b] = s;
    }
    __syncthreads();

    // staging + ldmatrix lane offsets
    const uint32_t wbase = sbase + OFF_A + (uint32_t)wid * A_WREG;
    const uint32_t aoff  = (uint32_t)((lane & 15) * (ASTR * 2) + (lane >> 4) * 16);
    // B pair-of-n8 ldsm4: groups (g=lane>>3): row = jb*8 + (g>>1)*8 + lane&7, kseg = g&1
    const uint32_t boffJ = (uint32_t)(((lane >> 4) * 8 + (lane & 7)) * (BSTR * 2)
                                      + ((lane >> 3) & 1) * 16);
    // j=4 ldsm2: all row addresses clamped to row 32 (cols all equal y)
    const uint32_t boff4 = (uint32_t)(32 * (BSTR * 2) + ((lane >> 3) & 1) * 16);
    const uint32_t kbase = (uint32_t)(kl * 1024);   // byte offset of this k-half
    // cp.async slots: row = lane>>1, seg = lane&1 (one 16B per comp per lane)
    const int fr = lane >> 1, fs = lane & 1;

    // epilogue identity (low warps): pair (lane, lane^1); par selects row r / r+8
    const int par = lane & 1;
    const int r_e = wr * 16 + (lane >> 2) + 8 * par;
    const int uo  = (lane >> 1) & 1;
    const int exi = (wid & 7) * 32 + lane;          // exchange slot (row-warp, lane)

    float cst[4] = {0.f, 0.f, 0.f, 0.f};            // low warps only

    for (int t = 0; t <= T_STEPS; ++t) {
        float d[5][4];
        #pragma unroll
        for (int j = 0; j < 5; ++j)
            #pragma unroll
            for (int q = 0; q < 4; ++q) d[j][q] = 0.f;

        if (t >= 1) {
            const __nv_bfloat16* hhi = g_hsp[t & 1][0];
            const __nv_bfloat16* hlo = g_hsp[t & 1][1];
            const size_t grow = (size_t)(wr * 16 + fr) * HID + kl * 512 + fs * 8;

            #define PREFETCH(m) do {                                         \
                uint32_t st = wbase + ((m) % 3) * A_WSTG                     \
                            + fr * (ASTR * 2) + fs * 16;                     \
                size_t go = grow + (size_t)(m) * KCH;                        \
                cp_async16(st,          hhi + go);                           \
                cp_async16(st + A_COMP, hlo + go);                           \
                cp_commit();                                                 \
            } while (0)

            PREFETCH(0);
            PREFETCH(1);

            for (int c = 0; c < NCHUNK; ++c) {
                if (c + 2 < NCHUNK) PREFETCH(c + 2);
                if (c + 2 < NCHUNK)       cp_wait2();
                else if (c + 2 == NCHUNK) cp_wait1();
                else                      cp_wait0();
                __syncwarp();

                const uint32_t aHi = wbase + (c % 3) * A_WSTG + aoff;
                const uint32_t kb  = kbase + (uint32_t)c * (KCH * 2);

                uint32_t ahi[4], alo[4];
                ldsm4(ahi, aHi);
                ldsm4(alo, aHi + A_COMP);

                #pragma unroll
                for (int jb = 0; jb < 2; ++jb) {     // n8 tile pairs (0,1),(2,3)
                    uint32_t bhi[4], blo[4];
                    uint32_t ba = sbase + boffJ + (uint32_t)(jb * 16) * (BSTR * 2) + kb;
                    ldsm4(bhi, ba + OFF_BHI);
                    ldsm4(blo, ba + OFF_BLO);
                    mma16816(d[jb * 2],     ahi, bhi);
                    mma16816(d[jb * 2 + 1], ahi, bhi + 2);
                    mma16816(d[jb * 2],     ahi, blo);
                    mma16816(d[jb * 2 + 1], ahi, blo + 2);
                    mma16816(d[jb * 2],     alo, bhi);
                    mma16816(d[jb * 2 + 1], alo, bhi + 2);
                }
                {                                    // j=4 (FC row, clamped)
                    uint32_t bhi[2], blo[2];
                    uint32_t ba = sbase + boff4 + kb;
                    ldsm2(bhi, ba + OFF_BHI);
                    ldsm2(blo, ba + OFF_BLO);
                    mma16816(d[4], ahi, bhi);
                    mma16816(d[4], ahi, blo);
                    mma16816(d[4], alo, bhi);
                }
            }
            #undef PREFETCH

            // ---------- k-half combine ----------
            __syncthreads();                 // all warps done with staging
            if (kl == 1) {
                float* e = exch + (size_t)exi * 21;
                #pragma unroll
                for (int j = 0; j < 5; ++j)
                    #pragma unroll
                    for (int q = 0; q < 4; ++q) e[j * 4 + q] = d[j][q];
            }
            __syncthreads();
            if (kl == 0) {
                const float* e = exch + (size_t)exi * 21;
                #pragma unroll
                for (int j = 0; j < 5; ++j)
                    #pragma unroll
                    for (int q = 0; q < 4; ++q) d[j][q] += e[j * 4 + q];
            }
        }

        // ---------- epilogue (low warps only) ----------
        if (kl == 0) {
            if (t >= 1 && uo == 0) {
                // j=4 tile: all cols equal y (clamped B rows) -> no shfl needed
                float yv = par ? d[4][2] : d[4][0];
                out[(size_t)r_e * (T_STEPS * PIECE) + (size_t)(t - 1) * PIECE + blk]
                    = yv + bfc;
            }

            if (t < T_STEPS) {
                __nv_bfloat16 hh[4], hl[4];
                #pragma unroll
                for (int j = 0; j < 4; ++j) {
                    int u = 2 * j + uo;
                    float gv[4];
                    if (t == 0) {
                        #pragma unroll
                        for (int g = 0; g < 4; ++g)
                            gv[g] = Xg[(u * 4 + g) * BATCH + r_e] + bsum[u * 4 + g];
                    } else {
                        float x0 = __shfl_xor_sync(0xffffffffu, d[j][0], 1);
                        float x1 = __shfl_xor_sync(0xffffffffu, d[j][1], 1);
                        float x2 = __shfl_xor_sync(0xffffffffu, d[j][2], 1);
                        float x3 = __shfl_xor_sync(0xffffffffu, d[j][3], 1);
                        if (par == 0) {      // row r: own = gates 0,1; partner = 2,3
                            gv[0] = d[j][0]; gv[1] = d[j][1]; gv[2] = x0; gv[3] = x1;
                        } else {             // row r+8: partner = 0,1; own = 2,3
                            gv[0] = x2; gv[1] = x3; gv[2] = d[j][2]; gv[3] = d[j][3];
                        }
                        #pragma unroll
                        for (int g = 0; g < 4; ++g) gv[g] += bsum[u * 4 + g];
                    }
                    float i_ = sigf(gv[0]), f_ = sigf(gv[1]);
                    float g_ = tanhf(gv[2]), o_ = sigf(gv[3]);
                    float cc = f_ * cst[j] + i_ * g_;
                    cst[j] = cc;
                    float hv = o_ * tanhf(cc);
                    __nv_bfloat16 hi = __float2bfloat16(hv);
                    hh[j] = hi;
                    hl[j] = __float2bfloat16(hv - __bfloat162float(hi));
                }
                __nv_bfloat16* dh = g_hsp[(t + 1) & 1][0]
                                  + (size_t)r_e * HID + blk * 8 + uo;
                __nv_bfloat16* dl = g_hsp[(t + 1) & 1][1]
                                  + (size_t)r_e * HID + blk * 8 + uo;
                #pragma unroll
                for (int j = 0; j < 4; ++j) { dh[2 * j] = hh[j]; dl[2 * j] = hl[j]; }
            }
        } else if (t >= 1 && t == T_STEPS) {
            // nothing: y handled by low warps (exchange gave them full sum)
        }

        if (t < T_STEPS)
            grid_bar();      // h_t visible to all CTAs before step t+1
    }
}

// ---------------- launch ----------------
extern "C" void kernel_launch(void* const* d_in, const int* in_sizes, int n_in,
                              void* d_out, int out_size)
{
    // metadata order: current_batch_size, z, w_ih, w_hh, b_ih, b_hh, W_fc, b_fc
    int off = (n_in >= 8) ? 1 : 0;
    const float* z    = (const float*)d_in[off + 0];
    const float* w_ih = (const float*)d_in[off + 1];
    const float* w_hh = (const float*)d_in[off + 2];
    const float* b_ih = (const float*)d_in[off + 3];
    const float* b_hh = (const float*)d_in[off + 4];
    const float* W_fc = (const float*)d_in[off + 5];
    const float* b_fc = (const float*)d_in[off + 6];

    cudaFuncSetAttribute(lstm_mma_kernel,
                         cudaFuncAttributeMaxDynamicSharedMemorySize, SMEM_BYTES);

    lstm_mma_kernel<<<NBLK, NTHR, SMEM_BYTES>>>(
        z, w_ih, w_hh, b_ih, b_hh, W_fc, b_fc, (float*)d_out);
}

// round 13
// speedup vs baseline: 1.2071x; 1.2071x over previous
#include <cuda_runtime.h>
#include <cuda_bf16.h>
#include <cstdint>

// Problem constants
#define T_STEPS 256
#define BATCH   128
#define HID     1024
#define LAT     128
#define PIECE   128

#define NBLK 128             // one CTA per 8 hidden units (32 gate cols); 1 CTA/SM
#define NTHR 256             // 8 warps: warp w owns batch rows w*16..w*16+15
#define KCH  32              // k per streamed chunk
#define NCHUNK 32

// B: 33 rows (32 gates + 1 FC) x 1024 k, row stride 1032 elems (2064 B)
#define BSTR 1032
#define OFF_BHI 0
#define OFF_BLO (33 * BSTR * 2)            // 68112
#define OFF_A   (2 * 33 * BSTR * 2)        // 136224 ; per-warp 4-stage staging
#define ASTR 40                            // A row: 32 k + 8 pad -> 80 B stride
#define A_COMP  (16 * ASTR * 2)            // 1280 B (one component, 16 rows)
#define A_WSTG  (2 * A_COMP)               // 2560 B (hi+lo)
#define A_WREG  (4 * A_WSTG)               // 10240 B per warp (4 stages)
#define OFF_MISC (OFF_A + 8 * A_WREG)      // 218144 ; bsum[32]
#define SMEM_BYTES (OFF_MISC + 256)        // 218400

typedef unsigned long long ull;

// Persistent state
__device__ __nv_bfloat16 g_hsp[2][2][BATCH * HID];  // [time buf][hi/lo][b][k]
__device__ unsigned g_bar;                          // monotonic grid barrier

// ---------------- helpers ----------------
__device__ __forceinline__ uint32_t smem_u32(const void* p) {
    uint32_t a;
    asm("{ .reg .u64 t; cvta.to.shared.u64 t, %1; cvt.u32.u64 %0, t; }"
        : "=r"(a) : "l"(p));
    return a;
}
__device__ __forceinline__ void cp_async16(uint32_t sdst, const void* gsrc) {
    asm volatile("cp.async.cg.shared.global [%0], [%1], 16;\n" :: "r"(sdst), "l"(gsrc));
}
__device__ __forceinline__ void cp_commit() { asm volatile("cp.async.commit_group;\n"); }
__device__ __forceinline__ void cp_wait0()  { asm volatile("cp.async.wait_group 0;\n"); }
__device__ __forceinline__ void cp_wait1()  { asm volatile("cp.async.wait_group 1;\n"); }
__device__ __forceinline__ void cp_wait2()  { asm volatile("cp.async.wait_group 2;\n"); }
__device__ __forceinline__ void cp_wait3()  { asm volatile("cp.async.wait_group 3;\n"); }

__device__ __forceinline__ void ldsm4(uint32_t* r, uint32_t addr) {
    asm volatile("ldmatrix.sync.aligned.m8n8.x4.shared.b16 {%0,%1,%2,%3}, [%4];"
                 : "=r"(r[0]), "=r"(r[1]), "=r"(r[2]), "=r"(r[3]) : "r"(addr));
}
__device__ __forceinline__ void ldsm2(uint32_t* r, uint32_t addr) {
    asm volatile("ldmatrix.sync.aligned.m8n8.x2.shared.b16 {%0,%1}, [%2];"
                 : "=r"(r[0]), "=r"(r[1]) : "r"(addr));
}
// mma.sync m16n8k16 row.col f32.bf16.bf16.f32
__device__ __forceinline__ void mma16816(float* d, const uint32_t* a, const uint32_t* b) {
    asm volatile(
        "mma.sync.aligned.m16n8k16.row.col.f32.bf16.bf16.f32 "
        "{%0,%1,%2,%3}, {%4,%5,%6,%7}, {%8,%9}, {%0,%1,%2,%3};"
        : "+f"(d[0]), "+f"(d[1]), "+f"(d[2]), "+f"(d[3])
        : "r"(a[0]), "r"(a[1]), "r"(a[2]), "r"(a[3]), "r"(b[0]), "r"(b[1]));
}
__device__ __forceinline__ float sigf(float x) { return 1.0f / (1.0f + __expf(-x)); }

// Grid barrier (128 co-resident CTAs; monotonic counter, graph-replay safe)
__device__ __forceinline__ void grid_bar() {
    __threadfence();
    __syncthreads();
    if (threadIdx.x == 0) {
        unsigned my = atomicAdd(&g_bar, 1u);
        unsigned target = my - (my % NBLK) + NBLK;
        while (*(volatile unsigned*)&g_bar < target) { __nanosleep(40); }
        __threadfence();
    }
    __syncthreads();
}

// ---------------- persistent mma.sync kernel ----------------
// Per step, per CTA: D[128 x 33] = h_split[128 x 1024] . B^T
//   B row n = u*4+g -> w_hh[g*HID+blk*8+u][:] ; row 32 -> W_fc[blk][:]
// Split bf16: D = Ahi.Bhi + Ahi.Blo + Alo.Bhi (fp32 accum)
// Warp-private A staging, 4 stages, 3 cp.async groups in flight, no block
// syncs inside the chunk loop.
extern "C" __global__ void __launch_bounds__(NTHR, 1)
lstm_mma_kernel(const float* __restrict__ z,
                const float* __restrict__ w_ih,
                const float* __restrict__ w_hh,
                const float* __restrict__ b_ih,
                const float* __restrict__ b_hh,
                const float* __restrict__ W_fc,
                const float* __restrict__ b_fc,
                float* __restrict__ out)
{
    extern __shared__ char smem[];
    const uint32_t sbase = smem_u32(smem);
    float* bsum = (float*)(smem + OFF_MISC);     // [32] gate biases
    float* Xg   = (float*)(smem + OFF_A);        // [32][128] f32, t=0 only (alias)

    const int tid  = threadIdx.x;
    const int blk  = blockIdx.x;
    const int wid  = tid >> 5;
    const int lane = tid & 31;

    // ---------- prologue: build B (split bf16), 33 rows ----------
    {
        uint4 zz = make_uint4(0, 0, 0, 0);
        uint4* bb = (uint4*)smem;
        for (int i = tid; i < (2 * 33 * BSTR * 2) / 16; i += NTHR) bb[i] = zz;
    }
    __syncthreads();
    for (int e = tid; e < 33 * HID; e += NTHR) {
        int n = e >> 10, k = e & 1023;
        float x;
        if (n < 32) {
            int u = n >> 2, g = n & 3;
            x = w_hh[(size_t)(g * HID + blk * 8 + u) * HID + k];
        } else {
            x = W_fc[(size_t)blk * HID + k];
        }
        __nv_bfloat16 hi = __float2bfloat16(x);
        __nv_bfloat16 lo = __float2bfloat16(x - __bfloat162float(hi));
        *(__nv_bfloat16*)(smem + OFF_BHI + ((size_t)n * BSTR + k) * 2) = hi;
        *(__nv_bfloat16*)(smem + OFF_BLO + ((size_t)n * BSTR + k) * 2) = lo;
    }
    if (tid < 32) {
        int u = tid >> 2, g = tid & 3;
        bsum[tid] = b_ih[g * HID + blk * 8 + u] + b_hh[g * HID + blk * 8 + u];
    }
    const float bfc = b_fc[blk];

    // Step-0 input gates: Xg[n][b] = z[b,:] . w_ih[row(n),:]
    for (int d = tid; d < 32 * BATCH; d += NTHR) {
        int n = d >> 7, b = d & 127;
        int u = n >> 2, g = n & 3;
        const float* wi = w_ih + (size_t)(g * HID + blk * 8 + u) * LAT;
        const float* zb = z + (size_t)b * LAT;
        float s = 0.f;
        #pragma unroll 4
        for (int l = 0; l < LAT; ++l) s += zb[l] * wi[l];
        Xg[n * BATCH + b] = s;
    }
    __syncthreads();

    // staging + ldmatrix lane offsets
    const uint32_t wbase = sbase + OFF_A + (uint32_t)wid * A_WREG;
    const uint32_t aoff  = (uint32_t)((lane & 15) * (ASTR * 2) + (lane >> 4) * 16);
    // B pair-of-n8 ldsm4: row = (lane>>4)*8 + (lane&7), kseg = (lane>>3)&1
    const uint32_t boffJ = (uint32_t)(((lane >> 4) * 8 + (lane & 7)) * (BSTR * 2)
                                      + ((lane >> 3) & 1) * 16);
    // j=4 ldsm2: all row addresses clamped to row 32 (cols all equal y)
    const uint32_t boff4 = (uint32_t)(32 * (BSTR * 2) + ((lane >> 3) & 1) * 16);
    // cp.async slots per component: s = lane (rows 0-7), lane+32 (rows 8-15)
    const int s0r = lane >> 2, s0s = lane & 3;
    const int s1r = (lane + 32) >> 2, s1s = lane & 3;

    // epilogue identity: pair (lane, lane^1); par selects row r / r+8
    const int par = lane & 1;
    const int r_e = wid * 16 + (lane >> 2) + 8 * par;
    const int uo  = (lane >> 1) & 1;          // unit offset within n8 tile

    float cst[4] = {0.f, 0.f, 0.f, 0.f};      // c-state: units 2j+uo, row r_e

    for (int t = 0; t <= T_STEPS; ++t) {
        float d[5][4];
        #pragma unroll
        for (int j = 0; j < 5; ++j)
            #pragma unroll
            for (int q = 0; q < 4; ++q) d[j][q] = 0.f;

        if (t >= 1) {
            const __nv_bfloat16* hhi = g_hsp[t & 1][0];
            const __nv_bfloat16* hlo = g_hsp[t & 1][1];
            const size_t rb0 = (size_t)(wid * 16 + s0r) * HID;
            const size_t rb1 = (size_t)(wid * 16 + s1r) * HID;

            // warp-local prefetch of chunk m into stage m%4 (one group each)
            #define PREFETCH(m) do {                                          \
                uint32_t st = wbase + ((m) & 3) * A_WSTG;                     \
                size_t kb = (size_t)(m) * KCH;                                \
                cp_async16(st + s0r * 80 + s0s * 16,          hhi + rb0 + kb + s0s * 8); \
                cp_async16(st + s1r * 80 + s1s * 16,          hhi + rb1 + kb + s1s * 8); \
                cp_async16(st + A_COMP + s0r * 80 + s0s * 16, hlo + rb0 + kb + s0s * 8); \
                cp_async16(st + A_COMP + s1r * 80 + s1s * 16, hlo + rb1 + kb + s1s * 8); \
                cp_commit();                                                  \
            } while (0)

            PREFETCH(0);
            PREFETCH(1);
            PREFETCH(2);

            for (int c = 0; c < NCHUNK; ++c) {
                if (c + 3 < NCHUNK) PREFETCH(c + 3);
                // wait until chunk c's group is complete (FIFO group order)
                if (c + 3 < NCHUNK)       cp_wait3();
                else if (c + 3 == NCHUNK) cp_wait2();
                else if (c + 2 == NCHUNK) cp_wait1();
                else                      cp_wait0();
                __syncwarp();

                const uint32_t aHi = wbase + (c & 3) * A_WSTG + aoff;
                const uint32_t aLo = aHi + A_COMP;
                const uint32_t kb  = (uint32_t)c * (KCH * 2);

                #pragma unroll
                for (int kk = 0; kk < 2; ++kk) {
                    uint32_t ahi[4], alo[4];
                    ldsm4(ahi, aHi + kk * 32);
                    ldsm4(alo, aLo + kk * 32);

                    #pragma unroll
                    for (int jb = 0; jb < 2; ++jb) {   // n8 tile pairs (0,1),(2,3)
                        uint32_t bhi[4], blo[4];
                        uint32_t ba = sbase + boffJ
                                    + (uint32_t)(jb * 16) * (BSTR * 2)
                                    + kb + kk * 32;
                        ldsm4(bhi, ba + OFF_BHI);
                        ldsm4(blo, ba + OFF_BLO);
                        mma16816(d[jb * 2],     ahi, bhi);
                        mma16816(d[jb * 2 + 1], ahi, bhi + 2);
                        mma16816(d[jb * 2],     ahi, blo);
                        mma16816(d[jb * 2 + 1], ahi, blo + 2);
                        mma16816(d[jb * 2],     alo, bhi);
                        mma16816(d[jb * 2 + 1], alo, bhi + 2);
                    }
                    {                                  // j=4 (FC row, clamped)
                        uint32_t bhi[2], blo[2];
                        uint32_t ba = sbase + boff4 + kb + kk * 32;
                        ldsm2(bhi, ba + OFF_BHI);
                        ldsm2(blo, ba + OFF_BLO);
                        mma16816(d[4], ahi, bhi);
                        mma16816(d[4], ahi, blo);
                        mma16816(d[4], alo, bhi);
                    }
                }
            }
            #undef PREFETCH
        }

        // ---------- epilogue ----------
        if (t >= 1 && uo == 0) {
            // j=4 tile: all cols equal y (clamped B rows) -> no shfl needed
            float yv = par ? d[4][2] : d[4][0];
            out[(size_t)r_e * (T_STEPS * PIECE) + (size_t)(t - 1) * PIECE + blk]
                = yv + bfc;
        }

        if (t < T_STEPS) {
            __nv_bfloat16 hh[4], hl[4];
            #pragma unroll
            for (int j = 0; j < 4; ++j) {
                int u = 2 * j + uo;
                float gv[4];
                if (t == 0) {
                    #pragma unroll
                    for (int g = 0; g < 4; ++g)
                        gv[g] = Xg[(u * 4 + g) * BATCH + r_e] + bsum[u * 4 + g];
                } else {
                    float x0 = __shfl_xor_sync(0xffffffffu, d[j][0], 1);
                    float x1 = __shfl_xor_sync(0xffffffffu, d[j][1], 1);
                    float x2 = __shfl_xor_sync(0xffffffffu, d[j][2], 1);
                    float x3 = __shfl_xor_sync(0xffffffffu, d[j][3], 1);
                    if (par == 0) {          // row r: own = gates 0,1; partner = 2,3
                        gv[0] = d[j][0]; gv[1] = d[j][1]; gv[2] = x0; gv[3] = x1;
                    } else {                 // row r+8: partner = 0,1; own = 2,3
                        gv[0] = x2; gv[1] = x3; gv[2] = d[j][2]; gv[3] = d[j][3];
                    }
                    #pragma unroll
                    for (int g = 0; g < 4; ++g) gv[g] += bsum[u * 4 + g];
                }
                float i_ = sigf(gv[0]), f_ = sigf(gv[1]);
                float g_ = tanhf(gv[2]), o_ = sigf(gv[3]);
                float cc = f_ * cst[j] + i_ * g_;
                cst[j] = cc;
                float hv = o_ * tanhf(cc);
                __nv_bfloat16 hi = __float2bfloat16(hv);
                hh[j] = hi;
                hl[j] = __float2bfloat16(hv - __bfloat162float(hi));
            }
            // store h_t split: k = blk*8 + 2j + uo, row r_e
            __nv_bfloat16* dh = g_hsp[(t + 1) & 1][0] + (size_t)r_e * HID + blk * 8 + uo;
            __nv_bfloat16* dl = g_hsp[(t + 1) & 1][1] + (size_t)r_e * HID + blk * 8 + uo;
            #pragma unroll
            for (int j = 0; j < 4; ++j) { dh[2 * j] = hh[j]; dl[2 * j] = hl[j]; }

            grid_bar();      // h_t visible to all CTAs before step t+1
        }
    }
}

// ---------------- launch ----------------
extern "C" void kernel_launch(void* const* d_in, const int* in_sizes, int n_in,
                              void* d_out, int out_size)
{
    // metadata order: current_batch_size, z, w_ih, w_hh, b_ih, b_hh, W_fc, b_fc
    int off = (n_in >= 8) ? 1 : 0;
    const float* z    = (const float*)d_in[off + 0];
    const float* w_ih = (const float*)d_in[off + 1];
    const float* w_hh = (const float*)d_in[off + 2];
    const float* b_ih = (const float*)d_in[off + 3];
    const float* b_hh = (const float*)d_in[off + 4];
    const float* W_fc = (const float*)d_in[off + 5];
    const float* b_fc = (const float*)d_in[off + 6];

    cudaFuncSetAttribute(lstm_mma_kernel,
                         cudaFuncAttributeMaxDynamicSharedMemorySize, SMEM_BYTES);

    lstm_mma_kernel<<<NBLK, NTHR, SMEM_BYTES>>>(
        z, w_ih, w_hh, b_ih, b_hh, W_fc, b_fc, (float*)d_out);
}

// round 14
// speedup vs baseline: 1.6050x; 1.3296x over previous
#include <cuda_runtime.h>
#include <cuda_fp16.h>
#include <cstdint>

// Problem constants
#define T_STEPS 256
#define BATCH   128
#define HID     1024
#define LAT     128
#define PIECE   128

#define NBLK 128             // one CTA per 8 hidden units (32 gate cols); 1 CTA/SM
#define NTHR 256             // 8 warps: warp w owns batch rows w*16..w*16+15
#define KCH  64              // k per streamed chunk
#define NCHUNK 16

// B: 33 rows (32 gates + 1 FC) x 1024 k, fp16 split hi/lo, row stride 1032 elems
#define BSTR 1032
#define OFF_BHI 0
#define OFF_BLO (33 * BSTR * 2)            // 68112
#define OFF_A   (2 * 33 * BSTR * 2)        // 136224 ; per-warp 4-stage staging
#define ASTRB 144                          // A row bytes: 64 k * 2 + 16 pad
#define A_STG  (16 * ASTRB)                // 2304 B per stage (16 rows)
#define A_WREG (4 * A_STG)                 // 9216 B per warp (4 stages)
#define OFF_MISC (OFF_A + 8 * A_WREG)      // 209952 ; bsum[32]
#define SMEM_BYTES (OFF_MISC + 256)        // 210208

typedef unsigned long long ull;

// Persistent state: h in single fp16 (2^-11 precision, |h|<=1)
__device__ __half g_h16[2][BATCH * HID];   // [time buf][b][k]
__device__ unsigned g_bar;                 // monotonic grid barrier

// ---------------- helpers ----------------
__device__ __forceinline__ uint32_t smem_u32(const void* p) {
    uint32_t a;
    asm("{ .reg .u64 t; cvta.to.shared.u64 t, %1; cvt.u32.u64 %0, t; }"
        : "=r"(a) : "l"(p));
    return a;
}
__device__ __forceinline__ void cp_async16(uint32_t sdst, const void* gsrc) {
    asm volatile("cp.async.cg.shared.global [%0], [%1], 16;\n" :: "r"(sdst), "l"(gsrc));
}
__device__ __forceinline__ void cp_commit() { asm volatile("cp.async.commit_group;\n"); }
__device__ __forceinline__ void cp_wait0()  { asm volatile("cp.async.wait_group 0;\n"); }
__device__ __forceinline__ void cp_wait1()  { asm volatile("cp.async.wait_group 1;\n"); }
__device__ __forceinline__ void cp_wait2()  { asm volatile("cp.async.wait_group 2;\n"); }
__device__ __forceinline__ void cp_wait3()  { asm volatile("cp.async.wait_group 3;\n"); }

__device__ __forceinline__ void ldsm4(uint32_t* r, uint32_t addr) {
    asm volatile("ldmatrix.sync.aligned.m8n8.x4.shared.b16 {%0,%1,%2,%3}, [%4];"
                 : "=r"(r[0]), "=r"(r[1]), "=r"(r[2]), "=r"(r[3]) : "r"(addr));
}
__device__ __forceinline__ void ldsm2(uint32_t* r, uint32_t addr) {
    asm volatile("ldmatrix.sync.aligned.m8n8.x2.shared.b16 {%0,%1}, [%2];"
                 : "=r"(r[0]), "=r"(r[1]) : "r"(addr));
}
// mma.sync m16n8k16 row.col f32.f16.f16.f32 (sm_80+)
__device__ __forceinline__ void mma16816(float* d, const uint32_t* a, const uint32_t* b) {
    asm volatile(
        "mma.sync.aligned.m16n8k16.row.col.f32.f16.f16.f32 "
        "{%0,%1,%2,%3}, {%4,%5,%6,%7}, {%8,%9}, {%0,%1,%2,%3};"
        : "+f"(d[0]), "+f"(d[1]), "+f"(d[2]), "+f"(d[3])
        : "r"(a[0]), "r"(a[1]), "r"(a[2]), "r"(a[3]), "r"(b[0]), "r"(b[1]));
}
__device__ __forceinline__ float sigf(float x) { return 1.0f / (1.0f + __expf(-x)); }

// Grid barrier (128 co-resident CTAs; monotonic counter, graph-replay safe)
__device__ __forceinline__ void grid_bar() {
    __threadfence();
    __syncthreads();
    if (threadIdx.x == 0) {
        unsigned my = atomicAdd(&g_bar, 1u);
        unsigned target = my - (my % NBLK) + NBLK;
        while (*(volatile unsigned*)&g_bar < target) { __nanosleep(40); }
        __threadfence();
    }
    __syncthreads();
}

// ---------------- persistent mma.sync kernel ----------------
// Per step, per CTA: D[128 x 33] = h[128 x 1024] . B^T
//   B row n = u*4+g -> w_hh[g*HID+blk*8+u][:] ; row 32 -> W_fc[blk][:]
// h single fp16; B split fp16: D = A.Bhi + A.Blo (fp32 accum)
// Warp-private A staging, 4 stages, 3 cp.async groups in flight, no block
// syncs inside the chunk loop.
extern "C" __global__ void __launch_bounds__(NTHR, 1)
lstm_mma_kernel(const float* __restrict__ z,
                const float* __restrict__ w_ih,
                const float* __restrict__ w_hh,
                const float* __restrict__ b_ih,
                const float* __restrict__ b_hh,
                const float* __restrict__ W_fc,
                const float* __restrict__ b_fc,
                float* __restrict__ out)
{
    extern __shared__ char smem[];
    const uint32_t sbase = smem_u32(smem);
    float* bsum = (float*)(smem + OFF_MISC);     // [32] gate biases
    float* Xg   = (float*)(smem + OFF_A);        // [32][128] f32, t=0 only (alias)

    const int tid  = threadIdx.x;
    const int blk  = blockIdx.x;
    const int wid  = tid >> 5;
    const int lane = tid & 31;

    // ---------- prologue: build B (split fp16), 33 rows ----------
    {
        uint4 zz = make_uint4(0, 0, 0, 0);
        uint4* bb = (uint4*)smem;
        for (int i = tid; i < (2 * 33 * BSTR * 2) / 16; i += NTHR) bb[i] = zz;
    }
    __syncthreads();
    for (int e = tid; e < 33 * HID; e += NTHR) {
        int n = e >> 10, k = e & 1023;
        float x;
        if (n < 32) {
            int u = n >> 2, g = n & 3;
            x = w_hh[(size_t)(g * HID + blk * 8 + u) * HID + k];
        } else {
            x = W_fc[(size_t)blk * HID + k];
        }
        __half hi = __float2half_rn(x);
        __half lo = __float2half_rn(x - __half2float(hi));
        *(__half*)(smem + OFF_BHI + ((size_t)n * BSTR + k) * 2) = hi;
        *(__half*)(smem + OFF_BLO + ((size_t)n * BSTR + k) * 2) = lo;
    }
    if (tid < 32) {
        int u = tid >> 2, g = tid & 3;
        bsum[tid] = b_ih[g * HID + blk * 8 + u] + b_hh[g * HID + blk * 8 + u];
    }
    const float bfc = b_fc[blk];

    // Step-0 input gates: Xg[n][b] = z[b,:] . w_ih[row(n),:]
    for (int d = tid; d < 32 * BATCH; d += NTHR) {
        int n = d >> 7, b = d & 127;
        int u = n >> 2, g = n & 3;
        const float* wi = w_ih + (size_t)(g * HID + blk * 8 + u) * LAT;
        const float* zb = z + (size_t)b * LAT;
        float s = 0.f;
        #pragma unroll 4
        for (int l = 0; l < LAT; ++l) s += zb[l] * wi[l];
        Xg[n * BATCH + b] = s;
    }
    __syncthreads();

    // staging + ldmatrix lane offsets
    const uint32_t wbase = sbase + OFF_A + (uint32_t)wid * A_WREG;
    const uint32_t aoff  = (uint32_t)((lane & 15) * ASTRB + (lane >> 4) * 16);
    // B pair-of-n8 ldsm4: row = (lane>>4)*8 + (lane&7), kseg = (lane>>3)&1
    const uint32_t boffJ = (uint32_t)(((lane >> 4) * 8 + (lane & 7)) * (BSTR * 2)
                                      + ((lane >> 3) & 1) * 16);
    // j=4 ldsm2: all row addresses clamped to row 32 (cols all equal y)
    const uint32_t boff4 = (uint32_t)(32 * (BSTR * 2) + ((lane >> 3) & 1) * 16);
    // cp.async slots: m = s*32 + lane, row = m>>3, seg = m&7 (4 slots/lane)
    // (coalesced: 32 lanes x 16B = 4 consecutive 128B global rows per slot)

    // epilogue identity: pair (lane, lane^1); par selects row r / r+8
    const int par = lane & 1;
    const int r_e = wid * 16 + (lane >> 2) + 8 * par;
    const int uo  = (lane >> 1) & 1;          // unit offset within n8 tile

    float cst[4] = {0.f, 0.f, 0.f, 0.f};      // c-state: units 2j+uo, row r_e

    for (int t = 0; t <= T_STEPS; ++t) {
        float d[5][4];
        #pragma unroll
        for (int j = 0; j < 5; ++j)
            #pragma unroll
            for (int q = 0; q < 4; ++q) d[j][q] = 0.f;

        if (t >= 1) {
            const __half* hsrc = g_h16[t & 1];

            // warp-local prefetch of chunk m into stage m%4 (one group each)
            #define PREFETCH(m) do {                                          \
                uint32_t st = wbase + ((m) & 3) * A_STG;                      \
                size_t kb = (size_t)(m) * KCH;                                \
                _Pragma("unroll")                                             \
                for (int s = 0; s < 4; ++s) {                                 \
                    int mm = s * 32 + lane; int rr = mm >> 3, sg = mm & 7;    \
                    cp_async16(st + rr * ASTRB + sg * 16,                     \
                               hsrc + (size_t)(wid * 16 + rr) * HID + kb + sg * 8); \
                }                                                             \
                cp_commit();                                                  \
            } while (0)

            PREFETCH(0);
            PREFETCH(1);
            PREFETCH(2);

            for (int c = 0; c < NCHUNK; ++c) {
                if (c + 3 < NCHUNK) PREFETCH(c + 3);
                // wait until chunk c's group is complete (FIFO group order)
                if (c + 3 < NCHUNK)       cp_wait3();
                else if (c + 3 == NCHUNK) cp_wait2();
                else if (c + 2 == NCHUNK) cp_wait1();
                else                      cp_wait0();
                __syncwarp();

                const uint32_t aB = wbase + (c & 3) * A_STG + aoff;
                const uint32_t kb = (uint32_t)c * (KCH * 2);

                #pragma unroll
                for (int kk = 0; kk < 4; ++kk) {      // 4 k16 sub-tiles
                    uint32_t a[4];
                    ldsm4(a, aB + kk * 32);

                    #pragma unroll
                    for (int jb = 0; jb < 2; ++jb) {  // n8 tile pairs (0,1),(2,3)
                        uint32_t bhi[4], blo[4];
                        uint32_t ba = sbase + boffJ
                                    + (uint32_t)(jb * 16) * (BSTR * 2)
                                    + kb + kk * 32;
                        ldsm4(bhi, ba + OFF_BHI);
                        ldsm4(blo, ba + OFF_BLO);
                        mma16816(d[jb * 2],     a, bhi);
                        mma16816(d[jb * 2 + 1], a, bhi + 2);
                        mma16816(d[jb * 2],     a, blo);
                        mma16816(d[jb * 2 + 1], a, blo + 2);
                    }
                    {                                 // j=4 (FC row, clamped)
                        uint32_t bhi[2], blo[2];
                        uint32_t ba = sbase + boff4 + kb + kk * 32;
                        ldsm2(bhi, ba + OFF_BHI);
                        ldsm2(blo, ba + OFF_BLO);
                        mma16816(d[4], a, bhi);
                        mma16816(d[4], a, blo);
                    }
                }
            }
            #undef PREFETCH
        }

        // ---------- epilogue ----------
        if (t >= 1 && uo == 0) {
            // j=4 tile: all cols equal y (clamped B rows) -> no shfl needed
            float yv = par ? d[4][2] : d[4][0];
            out[(size_t)r_e * (T_STEPS * PIECE) + (size_t)(t - 1) * PIECE + blk]
                = yv + bfc;
        }

        if (t < T_STEPS) {
            __half hh[4];
            #pragma unroll
            for (int j = 0; j < 4; ++j) {
                int u = 2 * j + uo;
                float gv[4];
                if (t == 0) {
                    #pragma unroll
                    for (int g = 0; g < 4; ++g)
                        gv[g] = Xg[(u * 4 + g) * BATCH + r_e] + bsum[u * 4 + g];
                } else {
                    float x0 = __shfl_xor_sync(0xffffffffu, d[j][0], 1);
                    float x1 = __shfl_xor_sync(0xffffffffu, d[j][1], 1);
                    float x2 = __shfl_xor_sync(0xffffffffu, d[j][2], 1);
                    float x3 = __shfl_xor_sync(0xffffffffu, d[j][3], 1);
                    if (par == 0) {          // row r: own = gates 0,1; partner = 2,3
                        gv[0] = d[j][0]; gv[1] = d[j][1]; gv[2] = x0; gv[3] = x1;
                    } else {                 // row r+8: partner = 0,1; own = 2,3
                        gv[0] = x2; gv[1] = x3; gv[2] = d[j][2]; gv[3] = d[j][3];
                    }
                    #pragma unroll
                    for (int g = 0; g < 4; ++g) gv[g] += bsum[u * 4 + g];
                }
                float i_ = sigf(gv[0]), f_ = sigf(gv[1]);
                float g_ = tanhf(gv[2]), o_ = sigf(gv[3]);
                float cc = f_ * cst[j] + i_ * g_;
                cst[j] = cc;
                hh[j] = __float2half_rn(o_ * tanhf(cc));
            }
            // store h_t: k = blk*8 + 2j + uo, row r_e
            __half* dh = g_h16[(t + 1) & 1] + (size_t)r_e * HID + blk * 8 + uo;
            #pragma unroll
            for (int j = 0; j < 4; ++j) dh[2 * j] = hh[j];

            grid_bar();      // h_t visible to all CTAs before step t+1
        }
    }
}

// ---------------- launch ----------------
extern "C" void kernel_launch(void* const* d_in, const int* in_sizes, int n_in,
                              void* d_out, int out_size)
{
    // metadata order: current_batch_size, z, w_ih, w_hh, b_ih, b_hh, W_fc, b_fc
    int off = (n_in >= 8) ? 1 : 0;
    const float* z    = (const float*)d_in[off + 0];
    const float* w_ih = (const float*)d_in[off + 1];
    const float* w_hh = (const float*)d_in[off + 2];
    const float* b_ih = (const float*)d_in[off + 3];
    const float* b_hh = (const float*)d_in[off + 4];
    const float* W_fc = (const float*)d_in[off + 5];
    const float* b_fc = (const float*)d_in[off + 6];

    cudaFuncSetAttribute(lstm_mma_kernel,
                         cudaFuncAttributeMaxDynamicSharedMemorySize, SMEM_BYTES);

    lstm_mma_kernel<<<NBLK, NTHR, SMEM_BYTES>>>(
        z, w_ih, w_hh, b_ih, b_hh, W_fc, b_fc, (float*)d_out);
}

// round 15
// speedup vs baseline: 1.9290x; 1.2019x over previous
#include <cuda_runtime.h>
#include <cuda_fp16.h>
#include <cstdint>

// Problem constants
#define T_STEPS 256
#define BATCH   128
#define HID     1024
#define LAT     128
#define PIECE   128

#define NBLK 128             // one CTA per 8 hidden units (32 gate cols); 1 CTA/SM
#define NTHR 256             // 8 warps: warp w owns batch rows w*16..w*16+15
#define KCH  64              // k per streamed chunk
#define NCHUNK 16
#define NSTG 8               // A staging stages per warp
#define NINFL 6              // cp.async groups in flight

// B: 33 rows (32 gates + 1 FC) x 1024 k, fp16 (hi only), row stride 1032 elems
#define BSTR 1032
#define OFF_BHI 0                          // 33*1032*2 = 68112 B
#define OFF_A   68224                      // aligned; per-warp 8-stage staging
#define ASTRB 144                          // A row bytes: 64 k * 2 + 16 pad
#define A_STG  (16 * ASTRB)                // 2304 B per stage (16 rows)
#define A_WREG (NSTG * A_STG)              // 18432 B per warp
#define OFF_MISC (OFF_A + 8 * A_WREG)      // 215680 ; bsum[32]
#define SMEM_BYTES (OFF_MISC + 256)        // 215936

typedef unsigned long long ull;

// Persistent state: h in fp16 (2^-11 precision, |h|<=1)
__device__ __half g_h16[2][BATCH * HID];   // [time buf][b][k]
__device__ unsigned g_bar;                 // monotonic grid barrier

// ---------------- helpers ----------------
__device__ __forceinline__ uint32_t smem_u32(const void* p) {
    uint32_t a;
    asm("{ .reg .u64 t; cvta.to.shared.u64 t, %1; cvt.u32.u64 %0, t; }"
        : "=r"(a) : "l"(p));
    return a;
}
__device__ __forceinline__ void cp_async16(uint32_t sdst, const void* gsrc) {
    asm volatile("cp.async.cg.shared.global [%0], [%1], 16;\n" :: "r"(sdst), "l"(gsrc));
}
__device__ __forceinline__ void cp_commit() { asm volatile("cp.async.commit_group;\n"); }
__device__ __forceinline__ void cp_waitN(int n) {
    switch (n) {
    case 0: asm volatile("cp.async.wait_group 0;\n"); break;
    case 1: asm volatile("cp.async.wait_group 1;\n"); break;
    case 2: asm volatile("cp.async.wait_group 2;\n"); break;
    case 3: asm volatile("cp.async.wait_group 3;\n"); break;
    case 4: asm volatile("cp.async.wait_group 4;\n"); break;
    case 5: asm volatile("cp.async.wait_group 5;\n"); break;
    default: asm volatile("cp.async.wait_group 6;\n"); break;
    }
}

__device__ __forceinline__ void ldsm4(uint32_t* r, uint32_t addr) {
    asm volatile("ldmatrix.sync.aligned.m8n8.x4.shared.b16 {%0,%1,%2,%3}, [%4];"
                 : "=r"(r[0]), "=r"(r[1]), "=r"(r[2]), "=r"(r[3]) : "r"(addr));
}
__device__ __forceinline__ void ldsm2(uint32_t* r, uint32_t addr) {
    asm volatile("ldmatrix.sync.aligned.m8n8.x2.shared.b16 {%0,%1}, [%2];"
                 : "=r"(r[0]), "=r"(r[1]) : "r"(addr));
}
// mma.sync m16n8k16 row.col f32.f16.f16.f32 (sm_80+)
__device__ __forceinline__ void mma16816(float* d, const uint32_t* a, const uint32_t* b) {
    asm volatile(
        "mma.sync.aligned.m16n8k16.row.col.f32.f16.f16.f32 "
        "{%0,%1,%2,%3}, {%4,%5,%6,%7}, {%8,%9}, {%0,%1,%2,%3};"
        : "+f"(d[0]), "+f"(d[1]), "+f"(d[2]), "+f"(d[3])
        : "r"(a[0]), "r"(a[1]), "r"(a[2]), "r"(a[3]), "r"(b[0]), "r"(b[1]));
}
__device__ __forceinline__ float sigf(float x) { return 1.0f / (1.0f + __expf(-x)); }

// Grid barrier (128 co-resident CTAs; monotonic counter, graph-replay safe)
__device__ __forceinline__ void grid_bar() {
    __threadfence();
    __syncthreads();
    if (threadIdx.x == 0) {
        unsigned my = atomicAdd(&g_bar, 1u);
        unsigned target = my - (my % NBLK) + NBLK;
        while (*(volatile unsigned*)&g_bar < target) { __nanosleep(40); }
        __threadfence();
    }
    __syncthreads();
}

// ---------------- persistent mma.sync kernel ----------------
// Per step, per CTA: D[128 x 33] = h[128 x 1024] . B^T
//   B row n = u*4+g -> w_hh[g*HID+blk*8+u][:] ; row 32 -> W_fc[blk][:]
// h fp16, B fp16 (hi only): D = A.B (fp32 accum)
// Warp-private A staging, 8 stages, 6 cp.async groups in flight, no block
// syncs inside the chunk loop.
extern "C" __global__ void __launch_bounds__(NTHR, 1)
lstm_mma_kernel(const float* __restrict__ z,
                const float* __restrict__ w_ih,
                const float* __restrict__ w_hh,
                const float* __restrict__ b_ih,
                const float* __restrict__ b_hh,
                const float* __restrict__ W_fc,
                const float* __restrict__ b_fc,
                float* __restrict__ out)
{
    extern __shared__ char smem[];
    const uint32_t sbase = smem_u32(smem);
    float* bsum = (float*)(smem + OFF_MISC);     // [32] gate biases
    float* Xg   = (float*)(smem + OFF_A);        // [32][128] f32, t=0 only (alias)

    const int tid  = threadIdx.x;
    const int blk  = blockIdx.x;
    const int wid  = tid >> 5;
    const int lane = tid & 31;

    // ---------- prologue: build B (fp16), 33 rows ----------
    {
        uint4 zz = make_uint4(0, 0, 0, 0);
        uint4* bb = (uint4*)smem;
        for (int i = tid; i < (33 * BSTR * 2) / 16; i += NTHR) bb[i] = zz;
    }
    __syncthreads();
    for (int e = tid; e < 33 * HID; e += NTHR) {
        int n = e >> 10, k = e & 1023;
        float x;
        if (n < 32) {
            int u = n >> 2, g = n & 3;
            x = w_hh[(size_t)(g * HID + blk * 8 + u) * HID + k];
        } else {
            x = W_fc[(size_t)blk * HID + k];
        }
        *(__half*)(smem + OFF_BHI + ((size_t)n * BSTR + k) * 2) = __float2half_rn(x);
    }
    if (tid < 32) {
        int u = tid >> 2, g = tid & 3;
        bsum[tid] = b_ih[g * HID + blk * 8 + u] + b_hh[g * HID + blk * 8 + u];
    }
    const float bfc = b_fc[blk];

    // Step-0 input gates: Xg[n][b] = z[b,:] . w_ih[row(n),:]
    for (int d = tid; d < 32 * BATCH; d += NTHR) {
        int n = d >> 7, b = d & 127;
        int u = n >> 2, g = n & 3;
        const float* wi = w_ih + (size_t)(g * HID + blk * 8 + u) * LAT;
        const float* zb = z + (size_t)b * LAT;
        float s = 0.f;
        #pragma unroll 4
        for (int l = 0; l < LAT; ++l) s += zb[l] * wi[l];
        Xg[n * BATCH + b] = s;
    }
    __syncthreads();

    // staging + ldmatrix lane offsets
    const uint32_t wbase = sbase + OFF_A + (uint32_t)wid * A_WREG;
    const uint32_t aoff  = (uint32_t)((lane & 15) * ASTRB + (lane >> 4) * 16);
    // B pair-of-n8 ldsm4: row = (lane>>4)*8 + (lane&7), kseg = (lane>>3)&1
    const uint32_t boffJ = (uint32_t)(((lane >> 4) * 8 + (lane & 7)) * (BSTR * 2)
                                      + ((lane >> 3) & 1) * 16);
    // j=4 ldsm2: all row addresses clamped to row 32 (cols all equal y)
    const uint32_t boff4 = (uint32_t)(32 * (BSTR * 2) + ((lane >> 3) & 1) * 16);

    // epilogue identity: pair (lane, lane^1); par selects row r / r+8
    const int par = lane & 1;
    const int r_e = wid * 16 + (lane >> 2) + 8 * par;
    const int uo  = (lane >> 1) & 1;          // unit offset within n8 tile

    float cst[4] = {0.f, 0.f, 0.f, 0.f};      // c-state: units 2j+uo, row r_e

    for (int t = 0; t <= T_STEPS; ++t) {
        float d[5][4];
        #pragma unroll
        for (int j = 0; j < 5; ++j)
            #pragma unroll
            for (int q = 0; q < 4; ++q) d[j][q] = 0.f;

        if (t >= 1) {
            const __half* hsrc = g_h16[t & 1];

            // warp-local prefetch of chunk m into stage m%8 (one group each)
            #define PREFETCH(m) do {                                          \
                uint32_t st = wbase + ((m) & 7) * A_STG;                      \
                size_t kb = (size_t)(m) * KCH;                                \
                _Pragma("unroll")                                             \
                for (int s = 0; s < 4; ++s) {                                 \
                    int mm = s * 32 + lane; int rr = mm >> 3, sg = mm & 7;    \
                    cp_async16(st + rr * ASTRB + sg * 16,                     \
                               hsrc + (size_t)(wid * 16 + rr) * HID + kb + sg * 8); \
                }                                                             \
                cp_commit();                                                  \
            } while (0)

            #pragma unroll
            for (int m = 0; m < NINFL; ++m) PREFETCH(m);

            for (int c = 0; c < NCHUNK; ++c) {
                if (c + NINFL < NCHUNK) PREFETCH(c + NINFL);
                // wait until chunk c's group is complete (FIFO group order)
                int pend = NCHUNK - 1 - c; if (pend > NINFL) pend = NINFL;
                cp_waitN(pend);
                __syncwarp();

                const uint32_t aB = wbase + (c & 7) * A_STG + aoff;
                const uint32_t kb = (uint32_t)c * (KCH * 2);

                #pragma unroll
                for (int kk = 0; kk < 4; ++kk) {      // 4 k16 sub-tiles
                    uint32_t a[4];
                    ldsm4(a, aB + kk * 32);

                    #pragma unroll
                    for (int jb = 0; jb < 2; ++jb) {  // n8 tile pairs (0,1),(2,3)
                        uint32_t bh[4];
                        uint32_t ba = sbase + boffJ
                                    + (uint32_t)(jb * 16) * (BSTR * 2)
                                    + kb + kk * 32;
                        ldsm4(bh, ba + OFF_BHI);
                        mma16816(d[jb * 2],     a, bh);
                        mma16816(d[jb * 2 + 1], a, bh + 2);
                    }
                    {                                 // j=4 (FC row, clamped)
                        uint32_t bh[2];
                        ldsm2(bh, sbase + boff4 + kb + kk * 32 + OFF_BHI);
                        mma16816(d[4], a, bh);
                    }
                }
            }
            #undef PREFETCH
        }

        // ---------- epilogue ----------
        if (t >= 1 && uo == 0) {
            // j=4 tile: all cols equal y (clamped B rows) -> no shfl needed
            float yv = par ? d[4][2] : d[4][0];
            out[(size_t)r_e * (T_STEPS * PIECE) + (size_t)(t - 1) * PIECE + blk]
                = yv + bfc;
        }

        if (t < T_STEPS) {
            __half hh[4];
            #pragma unroll
            for (int j = 0; j < 4; ++j) {
                int u = 2 * j + uo;
                float gv[4];
                if (t == 0) {
                    #pragma unroll
                    for (int g = 0; g < 4; ++g)
                        gv[g] = Xg[(u * 4 + g) * BATCH + r_e] + bsum[u * 4 + g];
                } else {
                    float x0 = __shfl_xor_sync(0xffffffffu, d[j][0], 1);
                    float x1 = __shfl_xor_sync(0xffffffffu, d[j][1], 1);
                    float x2 = __shfl_xor_sync(0xffffffffu, d[j][2], 1);
                    float x3 = __shfl_xor_sync(0xffffffffu, d[j][3], 1);
                    if (par == 0) {          // row r: own = gates 0,1; partner = 2,3
                        gv[0] = d[j][0]; gv[1] = d[j][1]; gv[2] = x0; gv[3] = x1;
                    } else {                 // row r+8: partner = 0,1; own = 2,3
                        gv[0] = x2; gv[1] = x3; gv[2] = d[j][2]; gv[3] = d[j][3];
                    }
                    #pragma unroll
                    for (int g = 0; g < 4; ++g) gv[g] += bsum[u * 4 + g];
                }
                float i_ = sigf(gv[0]), f_ = sigf(gv[1]);
                float g_ = tanhf(gv[2]), o_ = sigf(gv[3]);
                float cc = f_ * cst[j] + i_ * g_;
                cst[j] = cc;
                hh[j] = __float2half_rn(o_ * tanhf(cc));
            }
            // store h_t: k = blk*8 + 2j + uo, row r_e
            __half* dh = g_h16[(t + 1) & 1] + (size_t)r_e * HID + blk * 8 + uo;
            #pragma unroll
            for (int j = 0; j < 4; ++j) dh[2 * j] = hh[j];

            grid_bar();      // h_t visible to all CTAs before step t+1
        }
    }
}

// ---------------- launch ----------------
extern "C" void kernel_launch(void* const* d_in, const int* in_sizes, int n_in,
                              void* d_out, int out_size)
{
    // metadata order: current_batch_size, z, w_ih, w_hh, b_ih, b_hh, W_fc, b_fc
    int off = (n_in >= 8) ? 1 : 0;
    const float* z    = (const float*)d_in[off + 0];
    const float* w_ih = (const float*)d_in[off + 1];
    const float* w_hh = (const float*)d_in[off + 2];
    const float* b_ih = (const float*)d_in[off + 3];
    const float* b_hh = (const float*)d_in[off + 4];
    const float* W_fc = (const float*)d_in[off + 5];
    const float* b_fc = (const float*)d_in[off + 6];

    cudaFuncSetAttribute(lstm_mma_kernel,
                         cudaFuncAttributeMaxDynamicSharedMemorySize, SMEM_BYTES);

    lstm_mma_kernel<<<NBLK, NTHR, SMEM_BYTES>>>(
        z, w_ih, w_hh, b_ih, b_hh, W_fc, b_fc, (float*)d_out);
}

// round 16
// speedup vs baseline: 2.0423x; 1.0587x over previous
#include <cuda_runtime.h>
#include <cuda_fp16.h>
#include <cstdint>

// Problem constants
#define T_STEPS 256
#define BATCH   128
#define HID     1024
#define LAT     128
#define PIECE   128

// CTA = (batch half bh = blk>>6, unit group ug = blk&63): 64 batch rows x
// (16 hidden units = 64 gate cols) + 2 FC cols (p = ug*2, ug*2+1).
#define NBLK 128
#define NTHR 256             // 8 warps = 4 row-groups x 2 n-halves
#define KCH  64              // k per streamed chunk
#define NCHUNK 16
#define NSTG 8               // A staging stages per row-group
#define NINFL 6              // cp.async groups in flight

// B: 66 rows (64 gate cols + 2 FC) x 1024 k fp16, row stride 1032 elems
#define BSTR 1032
#define OFF_B 0                            // 66*1032*2 = 136224 B
#define OFF_A 136224                       // 4 row-group regions, 8 stages
#define ASTRB 144                          // A row bytes: 64 k * 2 + 16 pad
#define A_STG  (16 * ASTRB)                // 2304 B per stage (16 rows)
#define A_RREG (NSTG * A_STG)              // 18432 B per row-group
#define OFF_MISC (OFF_A + 4 * A_RREG)      // 209952 ; bsum[64]
#define SMEM_BYTES (OFF_MISC + 512)        // 210464

typedef unsigned long long ull;

// Persistent state: h in fp16 (2^-11 precision, |h|<=1)
__device__ __half g_h16[2][BATCH * HID];   // [time buf][b][k]
__device__ unsigned g_bar;                 // monotonic grid barrier

// ---------------- helpers ----------------
__device__ __forceinline__ uint32_t smem_u32(const void* p) {
    uint32_t a;
    asm("{ .reg .u64 t; cvta.to.shared.u64 t, %1; cvt.u32.u64 %0, t; }"
        : "=r"(a) : "l"(p));
    return a;
}
__device__ __forceinline__ void cp_async16(uint32_t sdst, const void* gsrc) {
    asm volatile("cp.async.cg.shared.global [%0], [%1], 16;\n" :: "r"(sdst), "l"(gsrc));
}
__device__ __forceinline__ void cp_commit() { asm volatile("cp.async.commit_group;\n"); }
__device__ __forceinline__ void cp_waitN(int n) {
    switch (n) {
    case 0: asm volatile("cp.async.wait_group 0;\n"); break;
    case 1: asm volatile("cp.async.wait_group 1;\n"); break;
    case 2: asm volatile("cp.async.wait_group 2;\n"); break;
    case 3: asm volatile("cp.async.wait_group 3;\n"); break;
    case 4: asm volatile("cp.async.wait_group 4;\n"); break;
    case 5: asm volatile("cp.async.wait_group 5;\n"); break;
    default: asm volatile("cp.async.wait_group 6;\n"); break;
    }
}
// named barrier over one row-group pair (64 threads); ids 1..4
__device__ __forceinline__ void bar_pair(int rg) {
    asm volatile("bar.sync %0, 64;" :: "r"(1 + rg) : "memory");
}

__device__ __forceinline__ void ldsm4(uint32_t* r, uint32_t addr) {
    asm volatile("ldmatrix.sync.aligned.m8n8.x4.shared.b16 {%0,%1,%2,%3}, [%4];"
                 : "=r"(r[0]), "=r"(r[1]), "=r"(r[2]), "=r"(r[3]) : "r"(addr));
}
__device__ __forceinline__ void ldsm2(uint32_t* r, uint32_t addr) {
    asm volatile("ldmatrix.sync.aligned.m8n8.x2.shared.b16 {%0,%1}, [%2];"
                 : "=r"(r[0]), "=r"(r[1]) : "r"(addr));
}
// mma.sync m16n8k16 row.col f32.f16.f16.f32
__device__ __forceinline__ void mma16816(float* d, const uint32_t* a, const uint32_t* b) {
    asm volatile(
        "mma.sync.aligned.m16n8k16.row.col.f32.f16.f16.f32 "
        "{%0,%1,%2,%3}, {%4,%5,%6,%7}, {%8,%9}, {%0,%1,%2,%3};"
        : "+f"(d[0]), "+f"(d[1]), "+f"(d[2]), "+f"(d[3])
        : "r"(a[0]), "r"(a[1]), "r"(a[2]), "r"(a[3]), "r"(b[0]), "r"(b[1]));
}
__device__ __forceinline__ float sigf(float x) { return 1.0f / (1.0f + __expf(-x)); }

// Grid barrier (128 co-resident CTAs; monotonic counter, graph-replay safe)
__device__ __forceinline__ void grid_bar() {
    __threadfence();
    __syncthreads();
    if (threadIdx.x == 0) {
        unsigned my = atomicAdd(&g_bar, 1u);
        unsigned target = my - (my % NBLK) + NBLK;
        while (*(volatile unsigned*)&g_bar < target) { __nanosleep(40); }
        __threadfence();
    }
    __syncthreads();
}

// ---------------- persistent mma.sync kernel ----------------
// Per step, per CTA: D[64 x 66] = h[rb..rb+63, 0..1023] . B^T
//   B row n<64: n = lu*4+g -> w_hh[g*HID + ug*16 + lu][:]
//   B rows 64,65 -> W_fc[ug*2 + 0/1][:]
// h fp16, B fp16: D = A.B (fp32 accum)
// Warps: rg = wid>>1 (rows rg*16..+15), nh = wid&1 (cols nh*32..+31 + FC 64+nh)
// Row-group pair shares staged A; per-chunk named barrier.
extern "C" __global__ void __launch_bounds__(NTHR, 1)
lstm_mma_kernel(const float* __restrict__ z,
                const float* __restrict__ w_ih,
                const float* __restrict__ w_hh,
                const float* __restrict__ b_ih,
                const float* __restrict__ b_hh,
                const float* __restrict__ W_fc,
                const float* __restrict__ b_fc,
                float* __restrict__ out)
{
    extern __shared__ char smem[];
    const uint32_t sbase = smem_u32(smem);
    float* bsum = (float*)(smem + OFF_MISC);     // [64] gate biases
    float* Xg   = (float*)(smem + OFF_A);        // [64][64] f32, t=0 only (alias)

    const int tid  = threadIdx.x;
    const int blk  = blockIdx.x;
    const int bh   = blk >> 6;       // batch half
    const int ug   = blk & 63;       // unit group (16 units)
    const int rb   = bh * 64;        // CTA's first batch row
    const int wid  = tid >> 5;
    const int lane = tid & 31;
    const int rg   = wid >> 1;       // row group: rows rg*16..+15 (local)
    const int nh   = wid & 1;        // n-half: cols nh*32..+31, FC row 64+nh

    // ---------- prologue: build B (fp16), 66 rows ----------
    for (int e = tid; e < 66 * HID; e += NTHR) {
        int n = e >> 10, k = e & 1023;
        float x;
        if (n < 64) {
            int lu = n >> 2, g = n & 3;
            x = w_hh[(size_t)(g * HID + ug * 16 + lu) * HID + k];
        } else {
            x = W_fc[(size_t)(ug * 2 + (n - 64)) * HID + k];
        }
        *(__half*)(smem + OFF_B + ((size_t)n * BSTR + k) * 2) = __float2half_rn(x);
    }
    if (tid < 64) {
        int lu = tid >> 2, g = tid & 3;
        bsum[tid] = b_ih[g * HID + ug * 16 + lu] + b_hh[g * HID + ug * 16 + lu];
    }
    const float bfc = b_fc[ug * 2 + nh];

    // Step-0 input gates: Xg[n][bl] = z[rb+bl,:] . w_ih[row(n),:]
    for (int d = tid; d < 64 * 64; d += NTHR) {
        int n = d >> 6, bl = d & 63;
        int lu = n >> 2, g = n & 3;
        const float* wi = w_ih + (size_t)(g * HID + ug * 16 + lu) * LAT;
        const float* zb = z + (size_t)(rb + bl) * LAT;
        float s = 0.f;
        #pragma unroll 4
        for (int l = 0; l < LAT; ++l) s += zb[l] * wi[l];
        Xg[n * 64 + bl] = s;
    }
    __syncthreads();

    // staging + ldmatrix lane offsets
    const uint32_t rbase = sbase + OFF_A + (uint32_t)rg * A_RREG;
    const uint32_t aoff  = (uint32_t)((lane & 15) * ASTRB + (lane >> 4) * 16);
    // B ldsm4-pair: row = nh*32 + (lane>>4)*8 + (lane&7), kseg = (lane>>3)&1
    const uint32_t boffJ = (uint32_t)((nh * 32 + (lane >> 4) * 8 + (lane & 7))
                                      * (BSTR * 2) + ((lane >> 3) & 1) * 16);
    // FC ldsm2: all rows clamped to row 64+nh (cols all equal y)
    const uint32_t boff4 = (uint32_t)((64 + nh) * (BSTR * 2) + ((lane >> 3) & 1) * 16);

    // epilogue identity: pair (lane, lane^1); par selects local row r / r+8
    const int par  = lane & 1;
    const int rloc = rg * 16 + (lane >> 2) + 8 * par;   // local batch row
    const int rgl  = rb + rloc;                         // global batch row
    const int uo   = (lane >> 1) & 1;                   // unit parity in n8 tile

    float cst[4] = {0.f, 0.f, 0.f, 0.f};  // c-state: local units nh*8+2j+uo, row rgl

    for (int t = 0; t <= T_STEPS; ++t) {
        float d[5][4];
        #pragma unroll
        for (int j = 0; j < 5; ++j)
            #pragma unroll
            for (int q = 0; q < 4; ++q) d[j][q] = 0.f;

        if (t >= 1) {
            const __half* hsrc = g_h16[t & 1];

            // warp nh loads rows nh*8..nh*8+7 of the row-group's 16-row stage
            #define PREFETCH(m) do {                                          \
                uint32_t st = rbase + ((m) & (NSTG - 1)) * A_STG;             \
                size_t kb = (size_t)(m) * KCH;                                \
                _Pragma("unroll")                                             \
                for (int s = 0; s < 2; ++s) {                                 \
                    int mm = s * 32 + lane; int rr = mm >> 3, sg = mm & 7;    \
                    cp_async16(st + (nh * 8 + rr) * ASTRB + sg * 16,          \
                               hsrc + (size_t)(rb + rg * 16 + nh * 8 + rr) * HID \
                                    + kb + sg * 8);                           \
                }                                                             \
                cp_commit();                                                  \
            } while (0)

            #pragma unroll
            for (int m = 0; m < NINFL; ++m) PREFETCH(m);

            for (int c = 0; c < NCHUNK; ++c) {
                if (c + NINFL < NCHUNK) PREFETCH(c + NINFL);
                int pend = NCHUNK - 1 - c; if (pend > NINFL) pend = NINFL;
                cp_waitN(pend);          // own half of stage c landed
                bar_pair(rg);            // peer's half landed too

                const uint32_t aB = rbase + (c & (NSTG - 1)) * A_STG + aoff;
                const uint32_t kb = (uint32_t)c * (KCH * 2);

                #pragma unroll
                for (int kk = 0; kk < 4; ++kk) {      // 4 k16 sub-tiles
                    uint32_t a[4];
                    ldsm4(a, aB + kk * 32);

                    #pragma unroll
                    for (int jb = 0; jb < 2; ++jb) {  // local n8 tile pairs
                        uint32_t bhv[4];
                        uint32_t ba = sbase + OFF_B + boffJ
                                    + (uint32_t)(jb * 16) * (BSTR * 2)
                                    + kb + kk * 32;
                        ldsm4(bhv, ba);
                        mma16816(d[jb * 2],     a, bhv);
                        mma16816(d[jb * 2 + 1], a, bhv + 2);
                    }
                    {                                 // FC row (clamped)
                        uint32_t bhv[2];
                        ldsm2(bhv, sbase + OFF_B + boff4 + kb + kk * 32);
                        mma16816(d[4], a, bhv);
                    }
                }
            }
            #undef PREFETCH
        }

        // ---------- epilogue ----------
        if (t >= 1 && uo == 0) {
            // FC tile: all cols equal y (clamped B rows) -> no shfl needed
            float yv = par ? d[4][2] : d[4][0];
            out[(size_t)rgl * (T_STEPS * PIECE) + (size_t)(t - 1) * PIECE
                + (ug * 2 + nh)] = yv + bfc;
        }

        if (t < T_STEPS) {
            __half hh[4];
            #pragma unroll
            for (int j = 0; j < 4; ++j) {
                int lu = nh * 8 + 2 * j + uo;         // local unit 0..15
                float gv[4];
                if (t == 0) {
                    #pragma unroll
                    for (int g = 0; g < 4; ++g)
                        gv[g] = Xg[(lu * 4 + g) * 64 + rloc] + bsum[lu * 4 + g];
                } else {
                    float x0 = __shfl_xor_sync(0xffffffffu, d[j][0], 1);
                    float x1 = __shfl_xor_sync(0xffffffffu, d[j][1], 1);
                    float x2 = __shfl_xor_sync(0xffffffffu, d[j][2], 1);
                    float x3 = __shfl_xor_sync(0xffffffffu, d[j][3], 1);
                    if (par == 0) {          // row r: own = gates 0,1; partner = 2,3
                        gv[0] = d[j][0]; gv[1] = d[j][1]; gv[2] = x0; gv[3] = x1;
                    } else {                 // row r+8: partner = 0,1; own = 2,3
                        gv[0] = x2; gv[1] = x3; gv[2] = d[j][2]; gv[3] = d[j][3];
                    }
                    #pragma unroll
                    for (int g = 0; g < 4; ++g) gv[g] += bsum[lu * 4 + g];
                }
                float i_ = sigf(gv[0]), f_ = sigf(gv[1]);
                float g_ = tanhf(gv[2]), o_ = sigf(gv[3]);
                float cc = f_ * cst[j] + i_ * g_;
                cst[j] = cc;
                hh[j] = __float2half_rn(o_ * tanhf(cc));
            }
            // store h_t: k = ug*16 + nh*8 + 2j + uo, row rgl
            __half* dh = g_h16[(t + 1) & 1] + (size_t)rgl * HID
                       + ug * 16 + nh * 8 + uo;
            #pragma unroll
            for (int j = 0; j < 4; ++j) dh[2 * j] = hh[j];

            grid_bar();      // h_t visible to all CTAs before step t+1
        }
    }
}

// ---------------- launch ----------------
extern "C" void kernel_launch(void* const* d_in, const int* in_sizes, int n_in,
                              void* d_out, int out_size)
{
    // metadata order: current_batch_size, z, w_ih, w_hh, b_ih, b_hh, W_fc, b_fc
    int off = (n_in >= 8) ? 1 : 0;
    const float* z    = (const float*)d_in[off + 0];
    const float* w_ih = (const float*)d_in[off + 1];
    const float* w_hh = (const float*)d_in[off + 2];
    const float* b_ih = (const float*)d_in[off + 3];
    const float* b_hh = (const float*)d_in[off + 4];
    const float* W_fc = (const float*)d_in[off + 5];
    const float* b_fc = (const float*)d_in[off + 6];

    cudaFuncSetAttribute(lstm_mma_kernel,
                         cudaFuncAttributeMaxDynamicSharedMemorySize, SMEM_BYTES);

    lstm_mma_kernel<<<NBLK, NTHR, SMEM_BYTES>>>(
        z, w_ih, w_hh, b_ih, b_hh, W_fc, b_fc, (float*)d_out);
}